// round 1
// baseline (speedup 1.0000x reference)
#include <cuda_runtime.h>
#include <math_constants.h>

// Problem constants
#define N_ROWS 262144
#define DIMK   512
#define DIMV   512

#define BLOCKS          1024
#define TPB             256
#define WARPS_PER_BLOCK (TPB / 32)
#define TOTAL_WARPS     (BLOCKS * WARPS_PER_BLOCK)   // 8192
#define ROWS_PER_WARP   (N_ROWS / TOTAL_WARPS)       // 32

#define TPB2 512   // finalize block (== DIMV)

// Scratch: per-warp online-softmax partials (device globals; no allocation)
__device__ float g_pmax[TOTAL_WARPS];
__device__ float g_psum[TOTAL_WARPS];
__device__ int   g_parg[TOTAL_WARPS];

__device__ __forceinline__ float dot_row(const float4* __restrict__ k4,
                                         const float4& q0, const float4& q1,
                                         const float4& q2, const float4& q3,
                                         int lane) {
    float4 a = k4[lane];
    float4 b = k4[lane + 32];
    float4 c = k4[lane + 64];
    float4 d = k4[lane + 96];
    float acc;
    acc  = a.x * q0.x; acc = fmaf(a.y, q0.y, acc); acc = fmaf(a.z, q0.z, acc); acc = fmaf(a.w, q0.w, acc);
    acc  = fmaf(b.x, q1.x, acc); acc = fmaf(b.y, q1.y, acc); acc = fmaf(b.z, q1.z, acc); acc = fmaf(b.w, q1.w, acc);
    acc  = fmaf(c.x, q2.x, acc); acc = fmaf(c.y, q2.y, acc); acc = fmaf(c.z, q2.z, acc); acc = fmaf(c.w, q2.w, acc);
    acc  = fmaf(d.x, q3.x, acc); acc = fmaf(d.y, q3.y, acc); acc = fmaf(d.z, q3.z, acc); acc = fmaf(d.w, q3.w, acc);
    return acc;
}

__global__ __launch_bounds__(TPB) void logits_kernel(const float* __restrict__ keys,
                                                     const float* __restrict__ query) {
    const int warp_id = (blockIdx.x * TPB + threadIdx.x) >> 5;
    const int lane    = threadIdx.x & 31;

    // Query held in registers: each lane owns 16 floats (4 x float4), coalesced.
    const float4* q4 = (const float4*)query;
    const float4 q0 = q4[lane];
    const float4 q1 = q4[lane + 32];
    const float4 q2 = q4[lane + 64];
    const float4 q3 = q4[lane + 96];

    float m = -CUDART_INF_F;
    float s = 0.0f;
    int   arg = 0;

    const int row0 = warp_id * ROWS_PER_WARP;

    #pragma unroll 1
    for (int r = 0; r < ROWS_PER_WARP; r += 2) {
        const int rowA = row0 + r;
        const int rowB = rowA + 1;
        const float4* kA = (const float4*)(keys + (size_t)rowA * DIMK);
        const float4* kB = (const float4*)(keys + (size_t)rowB * DIMK);

        float accA = dot_row(kA, q0, q1, q2, q3, lane);
        float accB = dot_row(kB, q0, q1, q2, q3, lane);

        // Interleaved warp reductions (independent shuffle chains)
        #pragma unroll
        for (int off = 16; off > 0; off >>= 1) {
            accA += __shfl_xor_sync(0xffffffffu, accA, off);
            accB += __shfl_xor_sync(0xffffffffu, accB, off);
        }

        // Online softmax update (all lanes hold the same value; redundant but branch-free)
        {
            float nm = fmaxf(m, accA);
            s = s * __expf(m - nm) + __expf(accA - nm);
            if (accA > m) arg = rowA;
            m = nm;
        }
        {
            float nm = fmaxf(m, accB);
            s = s * __expf(m - nm) + __expf(accB - nm);
            if (accB > m) arg = rowB;
            m = nm;
        }
    }

    if (lane == 0) {
        g_pmax[warp_id] = m;
        g_psum[warp_id] = s;
        g_parg[warp_id] = arg;
    }
}

__global__ __launch_bounds__(TPB2) void finalize_kernel(const float* __restrict__ values,
                                                        float* __restrict__ out) {
    __shared__ float sm[TPB2];
    __shared__ float ss[TPB2];
    __shared__ int   sa[TPB2];

    const int tid = threadIdx.x;

    float m = -CUDART_INF_F;
    float s = 0.0f;
    int   arg = 0;

    // Sequential, deterministic merge of per-warp partials
    for (int i = tid; i < TOTAL_WARPS; i += TPB2) {
        const float pm = g_pmax[i];
        const float ps = g_psum[i];
        const int   pa = g_parg[i];
        const float nm = fmaxf(m, pm);
        s = s * __expf(m - nm) + ps * __expf(pm - nm);
        if (pm > m) arg = pa;
        m = nm;
    }

    sm[tid] = m; ss[tid] = s; sa[tid] = arg;
    __syncthreads();

    // Deterministic tree merge
    for (int off = TPB2 / 2; off > 0; off >>= 1) {
        if (tid < off) {
            const float pm = sm[tid + off];
            const float ps = ss[tid + off];
            const float nm = fmaxf(sm[tid], pm);
            ss[tid] = ss[tid] * __expf(sm[tid] - nm) + ps * __expf(pm - nm);
            if (pm > sm[tid]) sa[tid] = sa[tid + off];
            sm[tid] = nm;
        }
        __syncthreads();
    }

    const int   best = sa[0];
    const float inv  = 1.0f / ss[0];

    // out[v] = values[best, v] / Z  (TPB2 == DIMV)
    out[tid] = values[(size_t)best * DIMV + tid] * inv;
}

extern "C" void kernel_launch(void* const* d_in, const int* in_sizes, int n_in,
                              void* d_out, int out_size) {
    const float* query  = (const float*)d_in[0];
    const float* keys   = (const float*)d_in[1];
    const float* values = (const float*)d_in[2];
    float* out = (float*)d_out;

    logits_kernel<<<BLOCKS, TPB>>>(keys, query);
    finalize_kernel<<<1, TPB2>>>(values, out);
}

// round 2
// speedup vs baseline: 1.2045x; 1.2045x over previous
#include <cuda_runtime.h>
#include <math_constants.h>

// Problem constants
#define N_ROWS 262144
#define DIMK   512
#define DIMV   512

#define BLOCKS          608              // 4 * 152 SMs — exactly one wave at occ=4
#define TPB             256
#define WARPS_PER_BLOCK (TPB / 32)
#define TOTAL_WARPS     (BLOCKS * WARPS_PER_BLOCK)   // 4864
#define TOTAL_PAIRS     (N_ROWS / 2)                 // 131072

// Scratch: per-BLOCK online-softmax partials + completion ticket
__device__ float g_bmax[BLOCKS];
__device__ float g_bsum[BLOCKS];
__device__ int   g_barg[BLOCKS];
__device__ int   g_ticket = 0;           // reset by last block each launch -> graph-replay safe

__device__ __forceinline__ float dot_row(const float4* __restrict__ k4,
                                         const float4& q0, const float4& q1,
                                         const float4& q2, const float4& q3,
                                         int lane) {
    // evict-streaming: keys have zero reuse, keep them out of L2's way
    float4 a = __ldcs(&k4[lane]);
    float4 b = __ldcs(&k4[lane + 32]);
    float4 c = __ldcs(&k4[lane + 64]);
    float4 d = __ldcs(&k4[lane + 96]);
    float acc;
    acc  = a.x * q0.x; acc = fmaf(a.y, q0.y, acc); acc = fmaf(a.z, q0.z, acc); acc = fmaf(a.w, q0.w, acc);
    acc  = fmaf(b.x, q1.x, acc); acc = fmaf(b.y, q1.y, acc); acc = fmaf(b.z, q1.z, acc); acc = fmaf(b.w, q1.w, acc);
    acc  = fmaf(c.x, q2.x, acc); acc = fmaf(c.y, q2.y, acc); acc = fmaf(c.z, q2.z, acc); acc = fmaf(c.w, q2.w, acc);
    acc  = fmaf(d.x, q3.x, acc); acc = fmaf(d.y, q3.y, acc); acc = fmaf(d.z, q3.z, acc); acc = fmaf(d.w, q3.w, acc);
    return acc;
}

// Merge (m2, s2, a2) into (m, s, arg) -- online softmax combine
__device__ __forceinline__ void osm_merge(float& m, float& s, int& arg,
                                          float m2, float s2, int a2) {
    float nm = fmaxf(m, m2);
    s = s * __expf(m - nm) + s2 * __expf(m2 - nm);
    if (m2 > m) arg = a2;
    m = nm;
}

__global__ __launch_bounds__(TPB, 4)
void fused_kernel(const float* __restrict__ keys,
                  const float* __restrict__ query,
                  const float* __restrict__ values,
                  float* __restrict__ out) {
    const int tid     = threadIdx.x;
    const int lane    = tid & 31;
    const int wid     = tid >> 5;
    const int gwarp   = blockIdx.x * WARPS_PER_BLOCK + wid;

    // Query in registers: each lane owns 16 floats (4 x float4), coalesced.
    const float4* q4 = (const float4*)query;
    const float4 q0 = q4[lane];
    const float4 q1 = q4[lane + 32];
    const float4 q2 = q4[lane + 64];
    const float4 q3 = q4[lane + 96];

    float m = -CUDART_INF_F;
    float s = 0.0f;
    int   arg = 0;

    // Grid-strided row pairs (persistent warps)
    #pragma unroll 1
    for (int p = gwarp; p < TOTAL_PAIRS; p += TOTAL_WARPS) {
        const int rowA = 2 * p;
        const int rowB = rowA + 1;
        const float4* kA = (const float4*)(keys + (size_t)rowA * DIMK);
        const float4* kB = (const float4*)(keys + (size_t)rowB * DIMK);

        float accA = dot_row(kA, q0, q1, q2, q3, lane);
        float accB = dot_row(kB, q0, q1, q2, q3, lane);

        #pragma unroll
        for (int off = 16; off > 0; off >>= 1) {
            accA += __shfl_xor_sync(0xffffffffu, accA, off);
            accB += __shfl_xor_sync(0xffffffffu, accB, off);
        }

        {
            float nm = fmaxf(m, accA);
            s = s * __expf(m - nm) + __expf(accA - nm);
            if (accA > m) arg = rowA;
            m = nm;
        }
        {
            float nm = fmaxf(m, accB);
            s = s * __expf(m - nm) + __expf(accB - nm);
            if (accB > m) arg = rowB;
            m = nm;
        }
    }

    // ---- Block-level merge of 8 warp partials ----
    __shared__ float sm_m[WARPS_PER_BLOCK];
    __shared__ float sm_s[WARPS_PER_BLOCK];
    __shared__ int   sm_a[WARPS_PER_BLOCK];
    __shared__ bool  is_last;

    if (lane == 0) {
        sm_m[wid] = m; sm_s[wid] = s; sm_a[wid] = arg;
    }
    __syncthreads();

    if (tid == 0) {
        float bm = sm_m[0], bs = sm_s[0];
        int   ba = sm_a[0];
        #pragma unroll
        for (int w = 1; w < WARPS_PER_BLOCK; w++)
            osm_merge(bm, bs, ba, sm_m[w], sm_s[w], sm_a[w]);
        g_bmax[blockIdx.x] = bm;
        g_bsum[blockIdx.x] = bs;
        g_barg[blockIdx.x] = ba;
        __threadfence();
        int old = atomicAdd(&g_ticket, 1);
        is_last = (old == BLOCKS - 1);
    }
    __syncthreads();

    if (!is_last) return;

    // ---- Last block: merge 608 block partials, write output ----
    __shared__ float fm[TPB];
    __shared__ float fs[TPB];
    __shared__ int   fa[TPB];

    float lm = -CUDART_INF_F, ls = 0.0f;
    int   la = 0;
    for (int i = tid; i < BLOCKS; i += TPB)
        osm_merge(lm, ls, la, g_bmax[i], g_bsum[i], g_barg[i]);

    fm[tid] = lm; fs[tid] = ls; fa[tid] = la;
    __syncthreads();

    for (int off = TPB / 2; off > 0; off >>= 1) {
        if (tid < off) {
            float m2 = fm[tid + off], s2 = fs[tid + off];
            int   a2 = fa[tid + off];
            float nm = fmaxf(fm[tid], m2);
            fs[tid] = fs[tid] * __expf(fm[tid] - nm) + s2 * __expf(m2 - nm);
            if (m2 > fm[tid]) fa[tid] = a2;
            fm[tid] = nm;
        }
        __syncthreads();
    }

    const int   best = fa[0];
    const float inv  = 1.0f / fs[0];
    const float* vrow = values + (size_t)best * DIMV;

    out[tid]       = vrow[tid]       * inv;
    out[tid + TPB] = vrow[tid + TPB] * inv;

    if (tid == 0) g_ticket = 0;   // reset for next graph replay
}

extern "C" void kernel_launch(void* const* d_in, const int* in_sizes, int n_in,
                              void* d_out, int out_size) {
    const float* query  = (const float*)d_in[0];
    const float* keys   = (const float*)d_in[1];
    const float* values = (const float*)d_in[2];
    float* out = (float*)d_out;

    fused_kernel<<<BLOCKS, TPB>>>(keys, query, values, out);
}